// round 8
// baseline (speedup 1.0000x reference)
#include <cuda_runtime.h>
#include <cuda_bf16.h>
#include <cuda_fp16.h>
#include <math.h>
#include <cstdint>

#define D 128
#define MAXN 50000
#define MAXE 800000

__device__ float g_support[MAXN * D];
__device__ unsigned g_hsup[MAXN * (D / 2)];   // support in bf16 packed pairs [m][k]
__device__ uint2 g_hin[MAXN * 32];            // input fp16: 32 uint2 (128 halves) per row
__device__ int   g_cnt[MAXN];
__device__ int   g_offs[MAXN];                // scan: global-excl start; after scatter: END
__device__ unsigned long long g_scanpub[64];  // (1<<63)|aggregate per scan block
__device__ int2  g_edge[MAXE];                // (col, val bits), binned by dest row
__device__ unsigned g_wt[D * (D / 2)];        // W^T bf16 packed pairs, [n][kpair]

__device__ __forceinline__ unsigned pack_bf16(float a, float b) {
    unsigned lo = (unsigned)__bfloat16_as_ushort(__float2bfloat16(a));
    unsigned hi = (unsigned)__bfloat16_as_ushort(__float2bfloat16(b));
    return lo | (hi << 16);
}

// ---------------- prep: convert input->fp16, zero cnt, zero scanpub, build W^T ----------------
// Block ranges: [0,nConv) convert; [nConv,nConv+nZero) zero cnt (+scanpub in first);
// [nConv+nZero, nConv+nZero+32) W^T.

__global__ void prep_kernel(const float* __restrict__ input,
                            const float* __restrict__ W,
                            int nConv, int nZero, int N) {
    int b = blockIdx.x;
    int t = threadIdx.x;
    if (b < nConv) {
        int i = b * 256 + t;
        if (i < N * 32) {
            float4 v = ((const float4*)input)[i];
            __half2 a = __floats2half2_rn(v.x, v.y);
            __half2 c = __floats2half2_rn(v.z, v.w);
            g_hin[i] = make_uint2(*(unsigned*)&a, *(unsigned*)&c);
        }
        return;
    }
    b -= nConv;
    if (b < nZero) {
        int i = b * 256 + t;
        if (i < N) g_cnt[i] = 0;
        if (b == 0 && t < 64) g_scanpub[t] = 0ull;
        return;
    }
    b -= nZero;
    {   // 32 blocks x 256 threads = 8192 = 128 n x 64 kpair
        int idx = b * 256 + t;
        int n  = idx & 127;
        int kp = idx >> 7;
        float v0 = __ldg(&W[(2 * kp) * D + n]);
        float v1 = __ldg(&W[(2 * kp + 1) * D + n]);
        g_wt[n * (D / 2) + kp] = pack_bf16(v0, v1);
    }
}

// ---------------- hist: 4 edges per thread ----------------

__global__ void hist_kernel(const int* __restrict__ row, int E4) {
    int t = blockIdx.x * blockDim.x + threadIdx.x;
    if (t >= E4) return;
    int4 r = ((const int4*)row)[t];
    atomicAdd(&g_cnt[r.x], 1);
    atomicAdd(&g_cnt[r.y], 1);
    atomicAdd(&g_cnt[r.z], 1);
    atomicAdd(&g_cnt[r.w], 1);
}

// ---------------- single-pass scan with decoupled lookback ----------------

__global__ void scan_kernel(int n) {
    __shared__ int s[1024];
    __shared__ int sbase;
    int b = blockIdx.x;
    int i = b * 1024 + threadIdx.x;
    int v = (i < n) ? g_cnt[i] : 0;
    s[threadIdx.x] = v;
    if (threadIdx.x == 0) sbase = 0;
    __syncthreads();
    for (int d = 1; d < 1024; d <<= 1) {
        int tv = (threadIdx.x >= d) ? s[threadIdx.x - d] : 0;
        __syncthreads();
        s[threadIdx.x] += tv;
        __syncthreads();
    }
    // publish this block's aggregate (single 64-bit word: ready bit | sum)
    if (threadIdx.x == 0) {
        unsigned long long pub = (1ull << 63) | (unsigned long long)(unsigned)s[1023];
        atomicExch(&g_scanpub[b], pub);
    }
    // lookback: thread j (< b) waits for block j's aggregate
    if (threadIdx.x < 64 && threadIdx.x < b) {
        unsigned long long v2;
        do { v2 = atomicAdd(&g_scanpub[threadIdx.x], 0ull); } while (!(v2 >> 63));
        atomicAdd(&sbase, (int)(v2 & 0x7fffffffull));
    }
    __syncthreads();
    if (i < n) g_offs[i] = sbase + s[threadIdx.x] - v;  // global exclusive start
}

// ---------------- scatter: 4 edges per thread ----------------

__global__ void scatter_kernel(const int* __restrict__ row, const int* __restrict__ col,
                               const float* __restrict__ vals, int E4) {
    int t = blockIdx.x * blockDim.x + threadIdx.x;
    if (t >= E4) return;
    int4   r = ((const int4*)row)[t];
    int4   c = ((const int4*)col)[t];
    float4 v = ((const float4*)vals)[t];
    int p0 = atomicAdd(&g_offs[r.x], 1);
    int p1 = atomicAdd(&g_offs[r.y], 1);
    int p2 = atomicAdd(&g_offs[r.z], 1);
    int p3 = atomicAdd(&g_offs[r.w], 1);
    g_edge[p0] = make_int2(c.x, __float_as_int(v.x));
    g_edge[p1] = make_int2(c.y, __float_as_int(v.y));
    g_edge[p2] = make_int2(c.z, __float_as_int(v.z));
    g_edge[p3] = make_int2(c.w, __float_as_int(v.w));
}

// ---------------- gather SpMM: support = (1-alpha)*A*input + alpha*h0 ----------------

__global__ void gather_kernel(const float* __restrict__ h0,
                              const float* __restrict__ alpha_p, int N) {
    int wid  = (blockIdx.x * blockDim.x + threadIdx.x) >> 5;
    int lane = threadIdx.x & 31;
    if (wid >= N) return;
    int end = g_offs[wid];            // END after scatter
    int beg = end - g_cnt[wid];

    float ax = 0.f, ay = 0.f, az = 0.f, aw = 0.f;
    int j = beg;
    for (; j + 8 <= end; j += 8) {
        int2 e[8];
#pragma unroll
        for (int q = 0; q < 8; q++) e[q] = __ldg(&g_edge[j + q]);
        uint2 x[8];
#pragma unroll
        for (int q = 0; q < 8; q++) x[q] = __ldg(&g_hin[(size_t)e[q].x * 32 + lane]);
#pragma unroll
        for (int q = 0; q < 8; q++) {
            float v = __int_as_float(e[q].y);
            float2 f0 = __half22float2(*(__half2*)&x[q].x);
            float2 f1 = __half22float2(*(__half2*)&x[q].y);
            ax = fmaf(v, f0.x, ax);
            ay = fmaf(v, f0.y, ay);
            az = fmaf(v, f1.x, az);
            aw = fmaf(v, f1.y, aw);
        }
    }
    for (; j < end; j++) {
        int2 e = __ldg(&g_edge[j]);
        float v = __int_as_float(e.y);
        uint2 x = __ldg(&g_hin[(size_t)e.x * 32 + lane]);
        float2 f0 = __half22float2(*(__half2*)&x.x);
        float2 f1 = __half22float2(*(__half2*)&x.y);
        ax = fmaf(v, f0.x, ax);
        ay = fmaf(v, f0.y, ay);
        az = fmaf(v, f1.x, az);
        aw = fmaf(v, f1.y, aw);
    }

    float a = *alpha_p, oma = 1.f - a;
    float4 h = ((const float4*)h0)[(size_t)wid * 32 + lane];
    float4 o = make_float4(fmaf(oma, ax, a * h.x),
                           fmaf(oma, ay, a * h.y),
                           fmaf(oma, az, a * h.z),
                           fmaf(oma, aw, a * h.w));
    ((float4*)g_support)[(size_t)wid * 32 + lane] = o;
    uint2 hb = make_uint2(pack_bf16(o.x, o.y), pack_bf16(o.z, o.w));
    ((uint2*)g_hsup)[(size_t)wid * 32 + lane] = hb;
}

// ---------------- HMMA GEMM: out = theta*(S@W) + (1-theta)*S ----------------

#define SB_STRIDE 66

__global__ void __launch_bounds__(256) gemm_mma_kernel(
        const float* __restrict__ lamda_p,
        const int* __restrict__ l_p,
        float* __restrict__ out, int N) {
    __shared__ unsigned sB[D * SB_STRIDE];

    int tid  = threadIdx.x;
    int lane = tid & 31;
    int w    = tid >> 5;
    int rowBase = blockIdx.x * 128 + w * 16;

    for (int i = tid; i < D * (D / 2); i += 256) {
        int n = i >> 6;
        int q = i & 63;
        sB[n * SB_STRIDE + q] = g_wt[i];
    }
    __syncthreads();

    int r0 = lane >> 2;
    int tg = lane & 3;

    int rowA = rowBase + r0;
    int rowB = rowA + 8;
    int rA = min(rowA, N - 1);
    int rB = min(rowB, N - 1);

    float acc[16][4];
#pragma unroll
    for (int nt = 0; nt < 16; nt++)
#pragma unroll
        for (int q = 0; q < 4; q++) acc[nt][q] = 0.f;

    const unsigned* gA = g_hsup;

#pragma unroll
    for (int k = 0; k < 8; k++) {
        unsigned a0 = __ldg(&gA[(size_t)rA * 64 + k * 8 + tg]);
        unsigned a1 = __ldg(&gA[(size_t)rB * 64 + k * 8 + tg]);
        unsigned a2 = __ldg(&gA[(size_t)rA * 64 + k * 8 + 4 + tg]);
        unsigned a3 = __ldg(&gA[(size_t)rB * 64 + k * 8 + 4 + tg]);
#pragma unroll
        for (int nt = 0; nt < 16; nt++) {
            int n = nt * 8 + r0;
            unsigned b0 = sB[n * SB_STRIDE + k * 8 + tg];
            unsigned b1 = sB[n * SB_STRIDE + k * 8 + 4 + tg];
            asm volatile(
                "mma.sync.aligned.m16n8k16.row.col.f32.bf16.bf16.f32 "
                "{%0,%1,%2,%3}, {%4,%5,%6,%7}, {%8,%9}, {%0,%1,%2,%3};"
                : "+f"(acc[nt][0]), "+f"(acc[nt][1]), "+f"(acc[nt][2]), "+f"(acc[nt][3])
                : "r"(a0), "r"(a1), "r"(a2), "r"(a3), "r"(b0), "r"(b1));
        }
    }

    float theta = logf(*lamda_p / (float)(*l_p) + 1.0f);
    float om = 1.0f - theta;

#pragma unroll
    for (int nt = 0; nt < 16; nt++) {
        int c = nt * 8 + tg * 2;
        if (rowA < N) {
            float2 s = *(const float2*)&g_support[(size_t)rowA * D + c];
            float2 o;
            o.x = fmaf(theta, acc[nt][0], om * s.x);
            o.y = fmaf(theta, acc[nt][1], om * s.y);
            *(float2*)&out[(size_t)rowA * D + c] = o;
        }
        if (rowB < N) {
            float2 s = *(const float2*)&g_support[(size_t)rowB * D + c];
            float2 o;
            o.x = fmaf(theta, acc[nt][2], om * s.x);
            o.y = fmaf(theta, acc[nt][3], om * s.y);
            *(float2*)&out[(size_t)rowB * D + c] = o;
        }
    }
}

// ---------------- launch ----------------

extern "C" void kernel_launch(void* const* d_in, const int* in_sizes, int n_in,
                              void* d_out, int out_size) {
    const float* input  = (const float*)d_in[0];
    const float* h0     = (const float*)d_in[1];
    const float* vals   = (const float*)d_in[2];
    const float* W      = (const float*)d_in[3];
    const float* lamda  = (const float*)d_in[4];
    const float* alpha  = (const float*)d_in[5];
    const int*   row    = (const int*)d_in[6];
    const int*   col    = (const int*)d_in[7];
    const int*   l      = (const int*)d_in[8];
    float* out = (float*)d_out;

    int N = in_sizes[0] / D;
    int E = in_sizes[2];

    int nConv = (N * 32 + 255) / 256;
    int nZero = (N + 255) / 256;
    prep_kernel<<<nConv + nZero + 32, 256>>>(input, W, nConv, nZero, N);

    int E4 = E / 4;                 // E = 800000, divisible by 4
    hist_kernel<<<(E4 + 255) / 256, 256>>>(row, E4);

    int nScanBlocks = (N + 1023) / 1024;   // 49 <= 64, all resident
    scan_kernel<<<nScanBlocks, 1024>>>(N);

    scatter_kernel<<<(E4 + 255) / 256, 256>>>(row, col, vals, E4);

    gather_kernel<<<(N * 32 + 255) / 256, 256>>>(h0, alpha, N);

    gemm_mma_kernel<<<(N + 127) / 128, 256>>>(lamda, l, out, N);
}

// round 9
// speedup vs baseline: 1.1200x; 1.1200x over previous
#include <cuda_runtime.h>
#include <cuda_fp16.h>
#include <math.h>
#include <cstdint>

#define D 128
#define MAXN 50000
#define MAXE 800000

__device__ uint2 g_hsup[MAXN * 32];           // support fp16: 32 uint2 (128 halves) per row
__device__ uint2 g_hin[MAXN * 32];            // input fp16: 32 uint2 per row
__device__ int   g_cnt[MAXN];
__device__ int   g_offs[MAXN];                // scan: global-excl start; after scatter: END
__device__ unsigned long long g_scanpub[64];  // (1<<63)|aggregate per scan block
__device__ int2  g_edge[MAXE];                // (col, val bits), binned by dest row
__device__ unsigned g_wt[D * (D / 2)];        // W'^T fp16 packed pairs, [n][kpair]

__device__ __forceinline__ unsigned pack_f16(float a, float b) {
    __half2 h = __floats2half2_rn(a, b);
    return *(unsigned*)&h;
}

// ---------------- prep: input->fp16, zero cnt/scanpub, build W' = theta*W + (1-theta)*I ----------------

__global__ void prep_kernel(const float* __restrict__ input,
                            const float* __restrict__ W,
                            const float* __restrict__ lamda_p,
                            const int* __restrict__ l_p,
                            int nConv, int nZero, int N) {
    int b = blockIdx.x;
    int t = threadIdx.x;
    if (b < nConv) {
        int i = b * 256 + t;
        if (i < N * 32) {
            float4 v = ((const float4*)input)[i];
            g_hin[i] = make_uint2(pack_f16(v.x, v.y), pack_f16(v.z, v.w));
        }
        return;
    }
    b -= nConv;
    if (b < nZero) {
        int i = b * 256 + t;
        if (i < N) g_cnt[i] = 0;
        if (b == 0 && t < 64) g_scanpub[t] = 0ull;
        return;
    }
    b -= nZero;
    {   // 32 blocks x 256 threads = 8192 = 128 n x 64 kpair: g_wt[n][kp] = (W'[2kp][n], W'[2kp+1][n])
        float theta = logf(*lamda_p / (float)(*l_p) + 1.0f);
        float om = 1.0f - theta;
        int idx = b * 256 + t;
        int n  = idx & 127;
        int kp = idx >> 7;
        int k0 = 2 * kp, k1 = 2 * kp + 1;
        float v0 = theta * __ldg(&W[k0 * D + n]) + (k0 == n ? om : 0.f);
        float v1 = theta * __ldg(&W[k1 * D + n]) + (k1 == n ? om : 0.f);
        g_wt[n * (D / 2) + kp] = pack_f16(v0, v1);
    }
}

// ---------------- hist: 4 edges per thread ----------------

__global__ void hist_kernel(const int* __restrict__ row, int E4) {
    int t = blockIdx.x * blockDim.x + threadIdx.x;
    if (t >= E4) return;
    int4 r = ((const int4*)row)[t];
    atomicAdd(&g_cnt[r.x], 1);
    atomicAdd(&g_cnt[r.y], 1);
    atomicAdd(&g_cnt[r.z], 1);
    atomicAdd(&g_cnt[r.w], 1);
}

// ---------------- single-pass scan with decoupled lookback ----------------

__global__ void scan_kernel(int n) {
    __shared__ int s[1024];
    __shared__ int sbase;
    int b = blockIdx.x;
    int i = b * 1024 + threadIdx.x;
    int v = (i < n) ? g_cnt[i] : 0;
    s[threadIdx.x] = v;
    if (threadIdx.x == 0) sbase = 0;
    __syncthreads();
    for (int d = 1; d < 1024; d <<= 1) {
        int tv = (threadIdx.x >= d) ? s[threadIdx.x - d] : 0;
        __syncthreads();
        s[threadIdx.x] += tv;
        __syncthreads();
    }
    if (threadIdx.x == 0) {
        unsigned long long pub = (1ull << 63) | (unsigned long long)(unsigned)s[1023];
        atomicExch(&g_scanpub[b], pub);
    }
    if (threadIdx.x < 64 && threadIdx.x < b) {
        unsigned long long v2;
        do { v2 = atomicAdd(&g_scanpub[threadIdx.x], 0ull); } while (!(v2 >> 63));
        atomicAdd(&sbase, (int)(v2 & 0x7fffffffull));
    }
    __syncthreads();
    if (i < n) g_offs[i] = sbase + s[threadIdx.x] - v;
}

// ---------------- scatter: 4 edges per thread ----------------

__global__ void scatter_kernel(const int* __restrict__ row, const int* __restrict__ col,
                               const float* __restrict__ vals, int E4) {
    int t = blockIdx.x * blockDim.x + threadIdx.x;
    if (t >= E4) return;
    int4   r = ((const int4*)row)[t];
    int4   c = ((const int4*)col)[t];
    float4 v = ((const float4*)vals)[t];
    int p0 = atomicAdd(&g_offs[r.x], 1);
    int p1 = atomicAdd(&g_offs[r.y], 1);
    int p2 = atomicAdd(&g_offs[r.z], 1);
    int p3 = atomicAdd(&g_offs[r.w], 1);
    g_edge[p0] = make_int2(c.x, __float_as_int(v.x));
    g_edge[p1] = make_int2(c.y, __float_as_int(v.y));
    g_edge[p2] = make_int2(c.z, __float_as_int(v.z));
    g_edge[p3] = make_int2(c.w, __float_as_int(v.w));
}

// ---------------- gather SpMM: S = (1-alpha)*A*input + alpha*h0, stored fp16 ----------------

__global__ void gather_kernel(const float* __restrict__ h0,
                              const float* __restrict__ alpha_p, int N) {
    int wid  = (blockIdx.x * blockDim.x + threadIdx.x) >> 5;
    int lane = threadIdx.x & 31;
    if (wid >= N) return;
    int end = g_offs[wid];            // END after scatter
    int beg = end - g_cnt[wid];

    float ax = 0.f, ay = 0.f, az = 0.f, aw = 0.f;
    int j = beg;
    for (; j + 8 <= end; j += 8) {
        int2 e[8];
#pragma unroll
        for (int q = 0; q < 8; q++) e[q] = __ldg(&g_edge[j + q]);
        uint2 x[8];
#pragma unroll
        for (int q = 0; q < 8; q++) x[q] = __ldg(&g_hin[(size_t)e[q].x * 32 + lane]);
#pragma unroll
        for (int q = 0; q < 8; q++) {
            float v = __int_as_float(e[q].y);
            float2 f0 = __half22float2(*(__half2*)&x[q].x);
            float2 f1 = __half22float2(*(__half2*)&x[q].y);
            ax = fmaf(v, f0.x, ax);
            ay = fmaf(v, f0.y, ay);
            az = fmaf(v, f1.x, az);
            aw = fmaf(v, f1.y, aw);
        }
    }
    for (; j < end; j++) {
        int2 e = __ldg(&g_edge[j]);
        float v = __int_as_float(e.y);
        uint2 x = __ldg(&g_hin[(size_t)e.x * 32 + lane]);
        float2 f0 = __half22float2(*(__half2*)&x.x);
        float2 f1 = __half22float2(*(__half2*)&x.y);
        ax = fmaf(v, f0.x, ax);
        ay = fmaf(v, f0.y, ay);
        az = fmaf(v, f1.x, az);
        aw = fmaf(v, f1.y, aw);
    }

    float a = *alpha_p, oma = 1.f - a;
    float4 h = ((const float4*)h0)[(size_t)wid * 32 + lane];
    float sx = fmaf(oma, ax, a * h.x);
    float sy = fmaf(oma, ay, a * h.y);
    float sz = fmaf(oma, az, a * h.z);
    float sw = fmaf(oma, aw, a * h.w);
    g_hsup[(size_t)wid * 32 + lane] = make_uint2(pack_f16(sx, sy), pack_f16(sz, sw));
}

// ---------------- HMMA GEMM: out = S @ W' (residual folded into W') ----------------

#define SB_STRIDE 66

__global__ void __launch_bounds__(256) gemm_mma_kernel(float* __restrict__ out, int N) {
    __shared__ unsigned sB[D * SB_STRIDE];

    int tid  = threadIdx.x;
    int lane = tid & 31;
    int w    = tid >> 5;
    int rowBase = blockIdx.x * 128 + w * 16;

    for (int i = tid; i < D * (D / 2); i += 256) {
        int n = i >> 6;
        int q = i & 63;
        sB[n * SB_STRIDE + q] = g_wt[i];
    }
    __syncthreads();

    int r0 = lane >> 2;
    int tg = lane & 3;

    int rowA = rowBase + r0;
    int rowB = rowA + 8;
    int rA = min(rowA, N - 1);
    int rB = min(rowB, N - 1);

    float acc[16][4];
#pragma unroll
    for (int nt = 0; nt < 16; nt++)
#pragma unroll
        for (int q = 0; q < 4; q++) acc[nt][q] = 0.f;

    const unsigned* gA = (const unsigned*)g_hsup;

#pragma unroll
    for (int k = 0; k < 8; k++) {
        unsigned a0 = __ldg(&gA[(size_t)rA * 64 + k * 8 + tg]);
        unsigned a1 = __ldg(&gA[(size_t)rB * 64 + k * 8 + tg]);
        unsigned a2 = __ldg(&gA[(size_t)rA * 64 + k * 8 + 4 + tg]);
        unsigned a3 = __ldg(&gA[(size_t)rB * 64 + k * 8 + 4 + tg]);
#pragma unroll
        for (int nt = 0; nt < 16; nt++) {
            int n = nt * 8 + r0;
            unsigned b0 = sB[n * SB_STRIDE + k * 8 + tg];
            unsigned b1 = sB[n * SB_STRIDE + k * 8 + 4 + tg];
            asm volatile(
                "mma.sync.aligned.m16n8k16.row.col.f32.f16.f16.f32 "
                "{%0,%1,%2,%3}, {%4,%5,%6,%7}, {%8,%9}, {%0,%1,%2,%3};"
                : "+f"(acc[nt][0]), "+f"(acc[nt][1]), "+f"(acc[nt][2]), "+f"(acc[nt][3])
                : "r"(a0), "r"(a1), "r"(a2), "r"(a3), "r"(b0), "r"(b1));
        }
    }

#pragma unroll
    for (int nt = 0; nt < 16; nt++) {
        int c = nt * 8 + tg * 2;
        if (rowA < N)
            *(float2*)&out[(size_t)rowA * D + c] = make_float2(acc[nt][0], acc[nt][1]);
        if (rowB < N)
            *(float2*)&out[(size_t)rowB * D + c] = make_float2(acc[nt][2], acc[nt][3]);
    }
}

// ---------------- launch ----------------

extern "C" void kernel_launch(void* const* d_in, const int* in_sizes, int n_in,
                              void* d_out, int out_size) {
    const float* input  = (const float*)d_in[0];
    const float* h0     = (const float*)d_in[1];
    const float* vals   = (const float*)d_in[2];
    const float* W      = (const float*)d_in[3];
    const float* lamda  = (const float*)d_in[4];
    const float* alpha  = (const float*)d_in[5];
    const int*   row    = (const int*)d_in[6];
    const int*   col    = (const int*)d_in[7];
    const int*   l      = (const int*)d_in[8];
    float* out = (float*)d_out;

    int N = in_sizes[0] / D;
    int E = in_sizes[2];

    int nConv = (N * 32 + 255) / 256;
    int nZero = (N + 255) / 256;
    prep_kernel<<<nConv + nZero + 32, 256>>>(input, W, lamda, l, nConv, nZero, N);

    int E4 = E / 4;
    hist_kernel<<<(E4 + 255) / 256, 256>>>(row, E4);

    int nScanBlocks = (N + 1023) / 1024;
    scan_kernel<<<nScanBlocks, 1024>>>(N);

    scatter_kernel<<<(E4 + 255) / 256, 256>>>(row, col, vals, E4);

    gather_kernel<<<(N * 32 + 255) / 256, 256>>>(h0, alpha, N);

    gemm_mma_kernel<<<(N + 127) / 128, 256>>>(out, N);
}